// round 16
// baseline (speedup 1.0000x reference)
#include <cuda_runtime.h>
#include <cuda_fp16.h>

// PolyConvFrame: x_0 = x; x_L = tanh(alphas[L]) * (Adj_norm @ x_{L-1}), L=1..3
// Adj_norm val_e = dinv[row_e]*w_e*dinv[col_e], dinv = deg>0 ? rsqrt(deg) : 0.
// Output [N, DEPTH+1, 64] fp32, out[i*256 + L*64 + d].
//
// R16 = R15 with the SpMM inner loop on the HFMA2 path:
//  - CSR entry = {col, half2(w,w)} (weight prepacked by k_fill).
//  - gather half2 row fragment; acc[j&3] = __hfma2(w2, f, acc[j&3]);
//    4 rotating half2 accumulators (<=deg/4 adds each) flushed to fp32 once
//    per row. Cuts ~half the issue slots of the previous cvt+FFMA loop.
// Everything else identical to R15 (packed count atomic, fused scan/alloc/
// mirror/slice0, raw fill, prescaled fp16 mirrors, aL*dinv epilogue).

#define N_NODE 100000
#define N_EDGE 1600000
#define D_FEAT 64
#define DEPTH  3
#define OUT_STRIDE 256                               // (DEPTH+1)*D_FEAT
#define SCAN_B ((N_NODE + 255) / 256)                // 391 blocks

__device__ unsigned long long g_pack[N_NODE];        // zeroed by k_scan after use
__device__ int   g_rowstart[N_NODE];
__device__ int   g_rowend[N_NODE];                   // start + padded count
__device__ int   g_cursor[N_NODE];
__device__ float g_dinv[N_NODE];
__device__ unsigned int g_grand;                     // zeroed by spmm<1> epilogue
// entry = {col, half2(w,w) bits}; +N_NODE pad, +8 guard (stays zero)
__device__ __align__(16) int2 g_csr[N_EDGE + N_NODE + 8];
__device__ __align__(128) __half g_mX[(size_t)N_NODE * D_FEAT];  // dinv*x
__device__ __align__(128) __half g_mA[(size_t)N_NODE * D_FEAT];  // dinv*x1
__device__ __align__(128) __half g_mB[(size_t)N_NODE * D_FEAT];  // dinv*x2

// --- per-block dtype probe (JAX x64-off coerces int64->int32) ---------------
__device__ __forceinline__ int probe_is64_block(const void* eidx) {
    __shared__ int s_is64;
    if (threadIdx.x < 32) {
        const long long* p = (const long long*)eidx;
        long long v = p[(size_t)threadIdx.x * (N_EDGE / 32)];
        unsigned bad = __ballot_sync(0xFFFFFFFFu, v < 0 || v >= N_NODE);
        if (threadIdx.x == 0) s_is64 = (bad == 0);
    }
    __syncthreads();
    return s_is64;
}

__device__ __forceinline__ int clampi(int v) {
    v = v < 0 ? 0 : v;
    return v >= N_NODE ? N_NODE - 1 : v;
}
__device__ __forceinline__ int ld_row(const void* e, int i, int is64) {
    long long v = is64 ? ((const long long*)e)[i] : (long long)((const int*)e)[i];
    return clampi((int)v);
}
__device__ __forceinline__ int ld_col(const void* e, int i, int is64) {
    long long v = is64 ? ((const long long*)e)[N_EDGE + i]
                       : (long long)((const int*)e)[N_EDGE + i];
    return clampi((int)v);
}

// Launch 1: one packed atomic per edge: pack[row] += (1<<48) | (w * 2^32).
// (deg stays fp32-accurate fixed point; w quantization only enters edge vals.)
__global__ void k_count(const void* __restrict__ eidx,
                        const float* __restrict__ w) {
    int is64 = probe_is64_block(eidx);
    int e = blockIdx.x * blockDim.x + threadIdx.x;
    if (e >= N_EDGE) return;
    int r = ld_row(eidx, e, is64);
    unsigned long long add =
        (1ull << 48) | (unsigned long long)(w[e] * 4294967296.0f);
    atomicAdd(&g_pack[r], add);
}

// Launch 2: unordered CSR allocation + dinv + fp16 mirror of x + out slice 0.
__global__ void k_scan(const float* __restrict__ x, float* __restrict__ out) {
    __shared__ int sh[256];
    __shared__ float sh_dinv[256];
    __shared__ unsigned sh_base;
    int tid = threadIdx.x;
    int i = blockIdx.x * 256 + tid;

    int cnt = 0;
    float deg = 0.f;
    if (i < N_NODE) {
        unsigned long long p = g_pack[i];
        cnt = (int)(p >> 48);
        deg = (float)((double)(p & 0xFFFFFFFFFFFFull) * (1.0 / 4294967296.0));
        g_pack[i] = 0ull;                            // restore zero-invariant
    }
    int c = (cnt + 1) & ~1;                          // even-padded count
    sh[tid] = c;
    __syncthreads();
    #pragma unroll
    for (int off = 1; off < 256; off <<= 1) {        // inclusive Hillis-Steele
        int t = (tid >= off) ? sh[tid - off] : 0;
        __syncthreads();
        sh[tid] += t;
        __syncthreads();
    }
    int incl = sh[tid];
    int total = sh[255];
    if (tid == 0) sh_base = atomicAdd(&g_grand, (unsigned)total);
    __syncthreads();

    float dv = 0.f;
    if (i < N_NODE) {
        int s = (int)sh_base + incl - c;
        g_rowstart[i] = s;
        g_cursor[i]   = s;
        g_rowend[i]   = s + c;
        if (cnt & 1) g_csr[s + cnt] = make_int2(0, 0);   // zero-weight pad
        dv = deg > 0.f ? rsqrtf(deg) : 0.f;
        g_dinv[i] = dv;
    }
    sh_dinv[tid] = dv;
    __syncthreads();

    // m_X = fp16(dinv * x) and out slice 0 = x, for this block's 256 nodes.
    int base_node = blockIdx.x * 256;
    #pragma unroll 1
    for (int t = tid; t < 256 * 32; t += 256) {
        int nl = t >> 5, el = t & 31;
        int node = base_node + nl;
        if (node < N_NODE) {
            float2 v = ((const float2*)x)[(size_t)node * 32 + el];
            float d = sh_dinv[nl];
            ((__half2*)g_mX)[(size_t)node * 32 + el] =
                __floats2half2_rn(d * v.x, d * v.y);
            ((float2*)(out + (size_t)node * OUT_STRIDE))[el] = v;
        }
    }
}

// Launch 3: bucket {col, half2(w,w)} into CSR.
__global__ void k_fill(const void* __restrict__ eidx,
                       const float* __restrict__ w) {
    int is64 = probe_is64_block(eidx);
    int e = blockIdx.x * blockDim.x + threadIdx.x;
    if (e >= N_EDGE) return;
    int r = ld_row(eidx, e, is64);
    int c = ld_col(eidx, e, is64);
    float wv = w[e];
    unsigned hw = (unsigned)__half_as_ushort(__float2half_rn(wv));
    unsigned wp = hw | (hw << 16);                   // half2(w, w)
    int pos = atomicAdd(&g_cursor[r], 1);
    g_csr[pos] = make_int2(c, (int)wp);
}

// One batch of 8 CSR entries at 16B-aligned even index i; half2 gathers;
// HFMA2 into 4 rotating half2 accumulators.
template <int PRED>
__device__ __forceinline__ void spmm_batch8(const __half* __restrict__ src,
                                            int i, int e, int lane,
                                            __half2 acc[4]) {
    const int4* p = (const int4*)(g_csr + i);
    int4 q[4];
    #pragma unroll
    for (int k = 0; k < 4; k++) q[k] = __ldg(p + k);

    int      col[8];
    unsigned wp[8];
    #pragma unroll
    for (int k = 0; k < 4; k++) {
        col[2 * k + 0] = q[k].x; wp[2 * k + 0] = (unsigned)q[k].y;
        col[2 * k + 1] = q[k].z; wp[2 * k + 1] = (unsigned)q[k].w;
    }
    if (PRED) {
        #pragma unroll
        for (int k = 0; k < 8; k++) {
            if (i + k >= e) { wp[k] = 0u; col[k] = 0; }
        }
    }
    __half2 f[8];
    #pragma unroll
    for (int k = 0; k < 8; k++)
        f[k] = __ldg((const __half2*)(src + (size_t)col[k] * D_FEAT) + lane);
    #pragma unroll
    for (int k = 0; k < 8; k++)
        acc[k & 3] = __hfma2(*(const __half2*)&wp[k], f[k], acc[k & 3]);
}

// Launches 4-6: SpMM layer L on prescaled mirrors; flush half accs to fp32,
// scale by aL*dinv[row]; write fp32 slice L and (L<3) the next mirror.
template <int L>
__global__ void __launch_bounds__(256)
k_spmm(float* __restrict__ out, const float* __restrict__ alphas) {
    int warp = (blockIdx.x * blockDim.x + threadIdx.x) >> 5;
    if (warp >= N_NODE) return;
    int lane = threadIdx.x & 31;

    int s = __ldg(&g_rowstart[warp]);                // even, 16B-aligned
    int e = __ldg(&g_rowend[warp]);                  // even (incl. pad)

    const __half* __restrict__ src =
        (L == 1) ? g_mX : (L == 2) ? g_mA : g_mB;

    __half2 acc[4];
    #pragma unroll
    for (int k = 0; k < 4; k++) acc[k] = __floats2half2_rn(0.f, 0.f);

    int i = s;
    int nfull = s + ((e - s) & ~7);
    #pragma unroll 1
    for (; i < nfull; i += 8)
        spmm_batch8<0>(src, i, e, lane, acc);
    if (i < e)                                       // 2..6 entries (even)
        spmm_batch8<1>(src, i, e, lane, acc);

    float2 a0 = __half22float2(acc[0]);
    float2 a1 = __half22float2(acc[1]);
    float2 a2 = __half22float2(acc[2]);
    float2 a3 = __half22float2(acc[3]);
    float ax = (a0.x + a1.x) + (a2.x + a3.x);
    float ay = (a0.y + a1.y) + (a2.y + a3.y);

    float dinv = __ldg(&g_dinv[warp]);
    float aL = tanhf(__ldg(&alphas[L]));
    float sc = aL * dinv;
    float rx = sc * ax, ry = sc * ay;

    ((float2*)(out + (size_t)warp * OUT_STRIDE + (size_t)L * D_FEAT))[lane] =
        make_float2(rx, ry);

    if (L == 1)
        ((__half2*)(g_mA + (size_t)warp * D_FEAT))[lane] =
            __floats2half2_rn(dinv * rx, dinv * ry);
    if (L == 2)
        ((__half2*)(g_mB + (size_t)warp * D_FEAT))[lane] =
            __floats2half2_rn(dinv * rx, dinv * ry);

    if (L == 1 && warp == 0 && lane == 0) g_grand = 0u;   // zero-invariant
}

extern "C" void kernel_launch(void* const* d_in, const int* in_sizes, int n_in,
                              void* d_out, int out_size) {
    const float* x      = (const float*)d_in[0];
    const void*  eidx   = d_in[1];                   // [2, E], int32 or int64
    const float* w      = (const float*)d_in[2];
    const float* alphas = (const float*)d_in[3];
    float* out = (float*)d_out;

    const int TB = 256;
    const int EB = (N_EDGE + TB - 1) / TB;
    const int SPMM_B = (N_NODE * 32 + TB - 1) / TB;  // warp per row

    k_count<<<EB, TB>>>(eidx, w);                    // launch 1
    k_scan<<<SCAN_B, 256>>>(x, out);                 // launch 2
    k_fill<<<EB, TB>>>(eidx, w);                     // launch 3
    k_spmm<1><<<SPMM_B, TB>>>(out, alphas);          // launch 4 (profiled)
    k_spmm<2><<<SPMM_B, TB>>>(out, alphas);          // launch 5
    k_spmm<3><<<SPMM_B, TB>>>(out, alphas);          // launch 6
}